// round 12
// baseline (speedup 1.0000x reference)
#include <cuda_runtime.h>
#include <cuda_bf16.h>

// AlphaRotatedIoULoss: loss = mean(1 - max(IoU_rot, 1e-6)^3) over N rotated-box pairs.
// Round 12: Green's-theorem edge integral (round 11) + PER-WARP coalesced smem
// staging. Each warp stages its own 64-pair region with 5 unrolled coalesced
// LDG.64 per tensor (2 L1 lines per warp-instr instead of 10), __syncwarp only
// (no block barrier -> inter-warp load/compute overlap preserved), then
// conflict-free stride-40B LDS.64 reads. Relative rotation via sincos(a1-a2).

#define MAX_BLOCKS 16384
static __device__ float g_part[MAX_BLOCKS];
static __device__ unsigned int g_cnt = 0;   // wraps back to 0 every launch

__device__ __forceinline__ float safe_inv(float dx) {
    // Antisymmetric: safe_inv(-x) == -safe_inv(x) exactly (incl. ±0).
    float dxs = (fabsf(dx) > 1e-12f) ? dx : copysignf(1e-12f, dx);
    return __fdividef(1.0f, dxs);
}

__device__ __forceinline__ float clampf(float v, float lo, float hi) {
    return fminf(fmaxf(v, lo), hi);
}

// Contribution of one polygon edge (sx,sy)->(sx+dx, sy+dy) to ∮x dy of the
// polygon clipped to [-W,W]x[-H,H]. hdx = 0.5*dx; inv_dx/inv_dy precomputed.
// csy/cvy are the y-clamped endpoint y's.
__device__ __forceinline__ float edge_contrib(
    float sx, float sy, float dx, float dy,
    float hdx, float inv_dx, float inv_dy,
    float csy, float cvy, float W, float H)
{
    // x-slab crossing interval [tx0, tx1] ⊂ [0,1]
    float tA = (-W - sx) * inv_dx;
    float tB = ( W - sx) * inv_dx;
    float tx0 = clampf(fminf(tA, tB), 0.0f, 1.0f);
    float tx1 = clampf(fmaxf(tA, tB), 0.0f, 1.0f);

    // y at the x-interval endpoints (for the boundary runs)
    float y0 = fmaf(tx0, dy, sy);
    float y1 = fmaf(tx1, dy, sy);

    // interior: intersect the y-crossing interval with [tx0, tx1]
    float uA = (-H - sy) * inv_dy;
    float uB = ( H - sy) * inv_dy;
    float t0 = clampf(fminf(uA, uB), tx0, tx1);
    float t1 = clampf(fmaxf(uA, uB), tx0, tx1);
    float xm = fmaf(hdx, t0 + t1, sx);           // x at midpoint of [t0,t1]
    float interior = dy * (t1 - t0) * xm;

    // boundary: low-t outside run at x = -XH, high-t run at x = +XH
    float XH  = copysignf(W, dx);
    float cy0 = clampf(y0, -H, H);
    float cy1 = clampf(y1, -H, H);
    return fmaf(XH, (cvy - cy1) - (cy0 - csy), interior);
}

// Full per-pair loss from the 10 box parameters.
__device__ __forceinline__ float pair_loss(
    float x1, float y1, float w1, float h1, float a1,
    float x2, float y2, float w2, float h2, float a2)
{
    float s2f, c2f, s, c;
    __sincosf(a2, &s2f, &c2f);
    __sincosf(a1 - a2, &s, &c);          // relative rotation directly

    // Box1 center in box2's local frame.
    float rx = x1 - x2, ry = y1 - y2;
    float lx =  rx * c2f + ry * s2f;
    float ly = -rx * s2f + ry * c2f;

    float hw1 = 0.5f * w1, hh1 = 0.5f * h1;
    float W = 0.5f * w2,  H = 0.5f * h2;

    float wx = hw1 * c, wy = hw1 * s;
    float hx = -hh1 * s, hy = hh1 * c;

    // Box1 corners (CCW) in box2 frame.
    float kx0 = lx - wx - hx, ky0 = ly - wy - hy;
    float kx1 = lx + wx - hx, ky1 = ly + wy - hy;
    float kx2 = lx + wx + hx, ky2 = ly + wy + hy;
    float kx3 = lx - wx + hx, ky3 = ly - wy + hy;

    // Edge vectors; central symmetry: edge2 = -edge0, edge3 = -edge1.
    float dx0 = kx1 - kx0, dy0 = ky1 - ky0;
    float dx1 = kx2 - kx1, dy1 = ky2 - ky1;
    float ix0 = safe_inv(dx0), iy0 = safe_inv(dy0);
    float ix1 = safe_inv(dx1), iy1 = safe_inv(dy1);
    float hdx0 = 0.5f * dx0, hdx1 = 0.5f * dx1;

    // Clamped corner y's (boundary-run endpoints).
    float cy0 = clampf(ky0, -H, H);
    float cy1 = clampf(ky1, -H, H);
    float cy2 = clampf(ky2, -H, H);
    float cy3 = clampf(ky3, -H, H);

    float acc;
    acc  = edge_contrib(kx0, ky0,  dx0,  dy0,  hdx0,  ix0,  iy0, cy0, cy1, W, H);
    acc += edge_contrib(kx1, ky1,  dx1,  dy1,  hdx1,  ix1,  iy1, cy1, cy2, W, H);
    acc += edge_contrib(kx2, ky2, -dx0, -dy0, -hdx0, -ix0, -iy0, cy2, cy3, W, H);
    acc += edge_contrib(kx3, ky3, -dx1, -dy1, -hdx1, -ix1, -iy1, cy3, cy0, W, H);

    float inter = fabsf(acc);
    float area1 = w1 * h1;
    float area2 = w2 * h2;
    float iou = __fdividef(inter, area1 + area2 - inter);
    iou = fmaxf(iou, 1e-6f);
    return 1.0f - iou * iou * iou;
}

__global__ __launch_bounds__(256) void arl_fused_kernel(
    const float* __restrict__ pred,
    const float* __restrict__ tgt,
    float* __restrict__ out,
    int n, float inv_n)
{
    // Per-warp staging buffers: 8 warps x 320 floats (64 pairs x 5) per tensor.
    __shared__ float sp[8][320];
    __shared__ float st[8][320];
    __shared__ float wsum[8];
    __shared__ bool s_last;

    int tid  = threadIdx.x;
    int lane = tid & 31;
    int wid  = tid >> 5;
    // Warp (block b, w) owns 64 consecutive pairs.
    int warpPair0 = (blockIdx.x * 8 + wid) * 64;
    float loss = 0.0f;

    if (warpPair0 + 64 <= n) {
        // Coalesced staging: 5 x LDG.64 per tensor, adjacent lanes read
        // adjacent 8B -> each warp-instruction touches 2 cache lines.
        const float2* pp = reinterpret_cast<const float2*>(pred + warpPair0 * 5);
        const float2* tp = reinterpret_cast<const float2*>(tgt  + warpPair0 * 5);
        float2* spw = reinterpret_cast<float2*>(&sp[wid][0]);
        float2* stw = reinterpret_cast<float2*>(&st[wid][0]);
        #pragma unroll
        for (int k = 0; k < 5; k++) {
            spw[k * 32 + lane] = __ldg(pp + k * 32 + lane);
            stw[k * 32 + lane] = __ldg(tp + k * 32 + lane);
        }
        __syncwarp();

        // Thread (lane) owns pairs warpPair0 + 2*lane, +1: floats [10*lane, +10).
        // 40B offset -> 8B-aligned float2 reads; word-stride 10 is conflict-free
        // per 16-lane LDS.64 phase.
        const float2* mp = reinterpret_cast<const float2*>(&sp[wid][lane * 10]);
        const float2* mt = reinterpret_cast<const float2*>(&st[wid][lane * 10]);
        float2 pa = mp[0], pb = mp[1], pc = mp[2], pd = mp[3], pe = mp[4];
        float2 ta = mt[0], tb = mt[1], tc = mt[2], td = mt[3], te = mt[4];

        float lA = pair_loss(pa.x, pa.y, pb.x, pb.y, pc.x,
                             ta.x, ta.y, tb.x, tb.y, tc.x);
        float lB = pair_loss(pc.y, pd.x, pd.y, pe.x, pe.y,
                             tc.y, td.x, td.y, te.x, te.y);
        loss = lA + lB;
    } else {
        // Tail warp: guarded scalar path (rare).
        #pragma unroll
        for (int q = 0; q < 2; q++) {
            int i = warpPair0 + 2 * lane + q;
            if (i < n) {
                const float* p = pred + 5 * i;
                const float* t = tgt + 5 * i;
                loss += pair_loss(__ldg(p + 0), __ldg(p + 1), __ldg(p + 2),
                                  __ldg(p + 3), __ldg(p + 4),
                                  __ldg(t + 0), __ldg(t + 1), __ldg(t + 2),
                                  __ldg(t + 3), __ldg(t + 4));
            }
        }
    }

    // Block reduction.
    #pragma unroll
    for (int off = 16; off > 0; off >>= 1)
        loss += __shfl_down_sync(0xffffffffu, loss, off);
    if (lane == 0) wsum[wid] = loss;
    __syncthreads();
    if (wid == 0) {
        float v = (lane < 8) ? wsum[lane] : 0.0f;
        #pragma unroll
        for (int off = 4; off > 0; off >>= 1)
            v += __shfl_down_sync(0xffu, v, off);
        if (lane == 0) {
            g_part[blockIdx.x] = v;
            __threadfence();
            // atomicInc wraps to 0 after gridDim.x increments -> counter ends
            // every launch at 0 (graph-replay deterministic).
            unsigned int old = atomicInc(&g_cnt, gridDim.x - 1);
            s_last = (old == gridDim.x - 1);
        }
    }
    __syncthreads();

    // Last block reduces the per-block partials and writes the mean.
    if (s_last) {
        double v = 0.0;
        for (int j = tid; j < gridDim.x; j += 256)
            v += (double)g_part[j];
        #pragma unroll
        for (int off = 16; off > 0; off >>= 1)
            v += __shfl_down_sync(0xffffffffu, v, off);
        __shared__ double dsum[8];
        if (lane == 0) dsum[wid] = v;
        __syncthreads();
        if (wid == 0) {
            double d = (lane < 8) ? dsum[lane] : 0.0;
            #pragma unroll
            for (int off = 4; off > 0; off >>= 1)
                d += __shfl_down_sync(0xffu, d, off);
            if (lane == 0)
                out[0] = (float)(d * (double)inv_n);
        }
    }
}

extern "C" void kernel_launch(void* const* d_in, const int* in_sizes, int n_in,
                              void* d_out, int out_size)
{
    const float* pred = (const float*)d_in[0];
    const float* tgt  = (const float*)d_in[1];
    float* out = (float*)d_out;
    int n = in_sizes[0] / 5;

    int pairs_per_block = 512;           // 8 warps x 64 pairs
    int blocks = (n + pairs_per_block - 1) / pairs_per_block;
    if (blocks > MAX_BLOCKS) blocks = MAX_BLOCKS;   // N=1e6 -> 1954, fits
    arl_fused_kernel<<<blocks, 256>>>(pred, tgt, out, n, 1.0f / (float)n);
}

// round 13
// speedup vs baseline: 1.1318x; 1.1318x over previous
#include <cuda_runtime.h>
#include <cuda_bf16.h>

// AlphaRotatedIoULoss: loss = mean(1 - max(IoU_rot, 1e-6)^3) over N rotated-box pairs.
// Round 13: revert per-warp staging (neutral x2); R11 direct-ldg structure +
// relative-rotation sincos + FFMA-refactored slab interval math (shared
// negated-inverse products replace FADD+FMUL pairs).

#define MAX_BLOCKS 16384
static __device__ float g_part[MAX_BLOCKS];
static __device__ unsigned int g_cnt = 0;   // wraps back to 0 every launch

__device__ __forceinline__ float safe_inv(float dx) {
    // Antisymmetric: safe_inv(-x) == -safe_inv(x) exactly (incl. ±0).
    float dxs = (fabsf(dx) > 1e-12f) ? dx : copysignf(1e-12f, dx);
    return __fdividef(1.0f, dxs);
}

__device__ __forceinline__ float clampf(float v, float lo, float hi) {
    return fminf(fmaxf(v, lo), hi);
}

// Contribution of one polygon edge (sx,sy)->(sx+dx, sy+dy) to ∮x dy of the
// polygon clipped to [-W,W]x[-H,H].
//   inv_dx/inv_dy : reciprocals of the edge deltas (clamped, antisymmetric)
//   Wix = W*inv_dx, Hiy = H*inv_dy : shared slab-offset products
//   hdx = 0.5*dx ; csy/cvy : y-clamped endpoint y's.
// Interval bounds as single FFMAs: (-W - sx)*inv = fma(sx, -inv, -Wix).
__device__ __forceinline__ float edge_contrib(
    float sx, float sy, float dx, float dy,
    float hdx, float inv_dx, float inv_dy,
    float Wix, float Hiy,
    float csy, float cvy, float W, float H)
{
    // x-slab crossing interval [tx0, tx1] ⊂ [0,1]
    float tA = fmaf(sx, -inv_dx, -Wix);
    float tB = fmaf(sx, -inv_dx,  Wix);
    float tx0 = clampf(fminf(tA, tB), 0.0f, 1.0f);
    float tx1 = clampf(fmaxf(tA, tB), 0.0f, 1.0f);

    // y at the x-interval endpoints (for the boundary runs)
    float y0 = fmaf(tx0, dy, sy);
    float y1 = fmaf(tx1, dy, sy);

    // interior: intersect the y-crossing interval with [tx0, tx1]
    float uA = fmaf(sy, -inv_dy, -Hiy);
    float uB = fmaf(sy, -inv_dy,  Hiy);
    float t0 = clampf(fminf(uA, uB), tx0, tx1);
    float t1 = clampf(fmaxf(uA, uB), tx0, tx1);
    float xm = fmaf(hdx, t0 + t1, sx);           // x at midpoint of [t0,t1]
    float interior = dy * (t1 - t0) * xm;

    // boundary: low-t outside run at x = -XH, high-t run at x = +XH
    float XH  = copysignf(W, dx);
    float cy0 = clampf(y0, -H, H);
    float cy1 = clampf(y1, -H, H);
    return fmaf(XH, (cvy - cy1) - (cy0 - csy), interior);
}

// Full per-pair loss from the 10 box parameters.
__device__ __forceinline__ float pair_loss(
    float x1, float y1, float w1, float h1, float a1,
    float x2, float y2, float w2, float h2, float a2)
{
    float s2f, c2f, s, c;
    __sincosf(a2, &s2f, &c2f);
    __sincosf(a1 - a2, &s, &c);          // relative rotation directly

    // Box1 center in box2's local frame.
    float rx = x1 - x2, ry = y1 - y2;
    float lx =  rx * c2f + ry * s2f;
    float ly = -rx * s2f + ry * c2f;

    float hw1 = 0.5f * w1, hh1 = 0.5f * h1;
    float W = 0.5f * w2,  H = 0.5f * h2;

    float wx = hw1 * c, wy = hw1 * s;
    float hx = -hh1 * s, hy = hh1 * c;

    // Box1 corners (CCW) in box2 frame.
    float kx0 = lx - wx - hx, ky0 = ly - wy - hy;
    float kx1 = lx + wx - hx, ky1 = ly + wy - hy;
    float kx2 = lx + wx + hx, ky2 = ly + wy + hy;
    float kx3 = lx - wx + hx, ky3 = ly - wy + hy;

    // Edge vectors; central symmetry: edge2 = -edge0, edge3 = -edge1.
    float dx0 = kx1 - kx0, dy0 = ky1 - ky0;
    float dx1 = kx2 - kx1, dy1 = ky2 - ky1;
    float ix0 = safe_inv(dx0), iy0 = safe_inv(dy0);
    float ix1 = safe_inv(dx1), iy1 = safe_inv(dy1);
    float hdx0 = 0.5f * dx0, hdx1 = 0.5f * dx1;

    // Shared slab-offset products (antiparallel edges reuse them: both the
    // inverse and the product flip sign together, so fma(sx,-inv,±Wix) stays
    // correct with negated arguments).
    float Wix0 = W * ix0, Wix1 = W * ix1;
    float Hiy0 = H * iy0, Hiy1 = H * iy1;

    // Clamped corner y's (boundary-run endpoints).
    float cy0 = clampf(ky0, -H, H);
    float cy1 = clampf(ky1, -H, H);
    float cy2 = clampf(ky2, -H, H);
    float cy3 = clampf(ky3, -H, H);

    float acc;
    acc  = edge_contrib(kx0, ky0,  dx0,  dy0,  hdx0,  ix0,  iy0,  Wix0,  Hiy0, cy0, cy1, W, H);
    acc += edge_contrib(kx1, ky1,  dx1,  dy1,  hdx1,  ix1,  iy1,  Wix1,  Hiy1, cy1, cy2, W, H);
    acc += edge_contrib(kx2, ky2, -dx0, -dy0, -hdx0, -ix0, -iy0, -Wix0, -Hiy0, cy2, cy3, W, H);
    acc += edge_contrib(kx3, ky3, -dx1, -dy1, -hdx1, -ix1, -iy1, -Wix1, -Hiy1, cy3, cy0, W, H);

    float inter = fabsf(acc);            // CCW -> acc >= 0; fabs folds to operand mod
    float area1 = w1 * h1;
    float area2 = w2 * h2;
    float iou = __fdividef(inter, area1 + area2 - inter);
    iou = fmaxf(iou, 1e-6f);
    return 1.0f - iou * iou * iou;
}

__global__ __launch_bounds__(256) void arl_fused_kernel(
    const float* __restrict__ pred,
    const float* __restrict__ tgt,
    float* __restrict__ out,
    int n, float inv_n)
{
    int tid = threadIdx.x;
    int gid = blockIdx.x * 256 + tid;
    int i0 = gid * 2;                    // this thread owns pairs i0, i0+1
    float loss = 0.0f;

    if (i0 + 1 < n) {
        // 80B per tensor per thread; base allocator-aligned, offset 8B-aligned.
        const float2* p2 = reinterpret_cast<const float2*>(pred + 10 * gid);
        const float2* t2 = reinterpret_cast<const float2*>(tgt + 10 * gid);
        float2 pa = __ldg(p2 + 0), pb = __ldg(p2 + 1), pc = __ldg(p2 + 2),
               pd = __ldg(p2 + 3), pe = __ldg(p2 + 4);
        float2 ta = __ldg(t2 + 0), tb = __ldg(t2 + 1), tc = __ldg(t2 + 2),
               td = __ldg(t2 + 3), te = __ldg(t2 + 4);

        float lA = pair_loss(pa.x, pa.y, pb.x, pb.y, pc.x,
                             ta.x, ta.y, tb.x, tb.y, tc.x);
        float lB = pair_loss(pc.y, pd.x, pd.y, pe.x, pe.y,
                             tc.y, td.x, td.y, te.x, te.y);
        loss = lA + lB;
    } else if (i0 < n) {
        const float* p = pred + 5 * i0;
        const float* t = tgt + 5 * i0;
        loss = pair_loss(__ldg(p + 0), __ldg(p + 1), __ldg(p + 2),
                         __ldg(p + 3), __ldg(p + 4),
                         __ldg(t + 0), __ldg(t + 1), __ldg(t + 2),
                         __ldg(t + 3), __ldg(t + 4));
    }

    // Block reduction.
    __shared__ float wsum[8];
    __shared__ bool s_last;
    #pragma unroll
    for (int off = 16; off > 0; off >>= 1)
        loss += __shfl_down_sync(0xffffffffu, loss, off);
    int lane = tid & 31;
    int wid  = tid >> 5;
    if (lane == 0) wsum[wid] = loss;
    __syncthreads();
    if (wid == 0) {
        float v = (lane < 8) ? wsum[lane] : 0.0f;
        #pragma unroll
        for (int off = 4; off > 0; off >>= 1)
            v += __shfl_down_sync(0xffu, v, off);
        if (lane == 0) {
            g_part[blockIdx.x] = v;
            __threadfence();
            // atomicInc wraps to 0 after gridDim.x increments -> counter ends
            // every launch at 0 (graph-replay deterministic).
            unsigned int old = atomicInc(&g_cnt, gridDim.x - 1);
            s_last = (old == gridDim.x - 1);
        }
    }
    __syncthreads();

    // Last block reduces the per-block partials and writes the mean.
    if (s_last) {
        double v = 0.0;
        for (int j = tid; j < gridDim.x; j += 256)
            v += (double)g_part[j];
        #pragma unroll
        for (int off = 16; off > 0; off >>= 1)
            v += __shfl_down_sync(0xffffffffu, v, off);
        __shared__ double dsum[8];
        if (lane == 0) dsum[wid] = v;
        __syncthreads();
        if (wid == 0) {
            double d = (lane < 8) ? dsum[lane] : 0.0;
            #pragma unroll
            for (int off = 4; off > 0; off >>= 1)
                d += __shfl_down_sync(0xffu, d, off);
            if (lane == 0)
                out[0] = (float)(d * (double)inv_n);
        }
    }
}

extern "C" void kernel_launch(void* const* d_in, const int* in_sizes, int n_in,
                              void* d_out, int out_size)
{
    const float* pred = (const float*)d_in[0];
    const float* tgt  = (const float*)d_in[1];
    float* out = (float*)d_out;
    int n = in_sizes[0] / 5;

    int pairs_per_block = 512;           // 256 threads x 2 pairs
    int blocks = (n + pairs_per_block - 1) / pairs_per_block;
    if (blocks > MAX_BLOCKS) blocks = MAX_BLOCKS;   // N=1e6 -> 1954, fits
    arl_fused_kernel<<<blocks, 256>>>(pred, tgt, out, n, 1.0f / (float)n);
}